// round 5
// baseline (speedup 1.0000x reference)
#include <cuda_runtime.h>

// ----------------------------------------------------------------------------
// SymplecticGyroceptron — R5: fully packed f32x2 datapath, 2 points/thread.
//
// All weights stored PRE-DUPLICATED in shared as 64-bit (w,w) words so the
// inner loop needs zero pack MOVs:
//   sPre[j]  = ( (wx,wx), (wy,wy) )          ulonglong2, one LDS.128
//   sBB[j]   = (b,b)                          u64,        one LDS.64
//   sGrad[j] = ( (wwx,wwx), (wwy,wwy) )       ulonglong2, one LDS.128
// where wwx = -eps*wout*wx, wwy = -eps*wout*wy (negated: t^2-1 trick).
//
// Per neuron per 2 points: 2 FFMA2 (pre) + 2 tanh.approx + 1 FFMA2 (t^2-1)
// + 2 FFMA2 (acc) + 3 LDS  ~= 10 issue slots (was ~14 in R4).
// launch_bounds(256,4) -> 64 regs, 32 warps/SM.
// ----------------------------------------------------------------------------

#define NEUR 64
#define NLAYERS 16   // 0..7 = psi (eps=1), 8..15 = ni (eps=0.01)

typedef unsigned long long u64;

__device__ ulonglong2 g_pre [NLAYERS * NEUR];
__device__ u64        g_bb  [NLAYERS * NEUR];
__device__ ulonglong2 g_grad[NLAYERS * NEUR];
__device__ float2     g_eta[NLAYERS];
__device__ float2     g_cs;

__device__ __forceinline__ u64 pack2(float lo, float hi) {
    u64 d; asm("mov.b64 %0, {%1, %2};" : "=l"(d) : "f"(lo), "f"(hi)); return d;
}
__device__ __forceinline__ void unpack2(u64 d, float& lo, float& hi) {
    asm("mov.b64 {%0, %1}, %2;" : "=f"(lo), "=f"(hi) : "l"(d));
}
__device__ __forceinline__ u64 ffma2(u64 a, u64 b, u64 c) {
    u64 d; asm("fma.rn.f32x2 %0, %1, %2, %3;" : "=l"(d) : "l"(a), "l"(b), "l"(c));
    return d;
}
__device__ __forceinline__ u64 fadd2(u64 a, u64 b) {
    u64 d; asm("add.rn.f32x2 %0, %1, %2;" : "=l"(d) : "l"(a), "l"(b));
    return d;
}
__device__ __forceinline__ u64 fmul2(u64 a, u64 b) {
    u64 d; asm("mul.rn.f32x2 %0, %1, %2;" : "=l"(d) : "l"(a), "l"(b));
    return d;
}
__device__ __forceinline__ float tanh_ap(float x) {
    float t; asm("tanh.approx.f32 %0, %1;" : "=f"(t) : "f"(x)); return t;
}

__global__ void prep_kernel(const float* __restrict__ theta0,
                            const float* __restrict__ psi_Win,
                            const float* __restrict__ psi_Wout,
                            const float* __restrict__ psi_b,
                            const float* __restrict__ psi_eta,
                            const float* __restrict__ ni_Win,
                            const float* __restrict__ ni_Wout,
                            const float* __restrict__ ni_b,
                            const float* __restrict__ ni_eta)
{
    int t = threadIdx.x;
    if (t < NLAYERS * NEUR) {
        int l = t >> 6;
        int j = t & 63;
        const float *Win, *Wout, *b;
        float eps;
        int i;
        if (l < 8) { i = l;     Win = psi_Win; Wout = psi_Wout; b = psi_b; eps = 1.0f;  }
        else       { i = l - 8; Win = ni_Win;  Wout = ni_Wout;  b = ni_b;  eps = 0.01f; }
        float w0 = Win[i * 128 + j];        // W_in[i][0][j]
        float w1 = Win[i * 128 + 64 + j];   // W_in[i][1][j]
        float bb = b[i * 64 + j];           // b_in[i][0][j]
        float wo = -Wout[i * 64 + j] * eps; // NEGATED eps*W_out (t^2-1 trick)
        ulonglong2 p; p.x = pack2(w0, w0);       p.y = pack2(w1, w1);
        ulonglong2 g; g.x = pack2(wo*w0, wo*w0); g.y = pack2(wo*w1, wo*w1);
        g_pre[t]  = p;
        g_bb[t]   = pack2(bb, bb);
        g_grad[t] = g;
    }
    if (t < NLAYERS) {
        const float* e = (t < 8) ? (psi_eta + t * 2) : (ni_eta + (t - 8) * 2);
        g_eta[t] = make_float2(e[0], e[1]);
    }
    if (t == 0) {
        float th = theta0[0];
        g_cs = make_float2(cosf(th), sinf(th));
    }
}

// grad_V for two packed points. Y0=(yA0,yB0), Y1=(yA1,yB1). Outputs packed.
__device__ __forceinline__ void grad2x2(const ulonglong2* __restrict__ sPre,
                                        const u64*        __restrict__ sBB,
                                        const ulonglong2* __restrict__ sGrad,
                                        u64 Y0, u64 Y1, u64 NEG1,
                                        u64& G0, u64& G1)
{
    u64 a0 = 0ull, a1 = 0ull, b0 = 0ull, b1 = 0ull;
#pragma unroll 4
    for (int j = 0; j < NEUR; j += 2) {
        {
            ulonglong2 wp = sPre[j];
            u64        bb = sBB[j];
            ulonglong2 wg = sGrad[j];
            u64 pre = ffma2(Y0, wp.x, ffma2(Y1, wp.y, bb));
            float pl, ph; unpack2(pre, pl, ph);
            u64 t = pack2(tanh_ap(pl), tanh_ap(ph));
            u64 t2m = ffma2(t, t, NEG1);           // t^2 - 1
            a0 = ffma2(t2m, wg.x, a0);
            a1 = ffma2(t2m, wg.y, a1);
        }
        {
            ulonglong2 wp = sPre[j + 1];
            u64        bb = sBB[j + 1];
            ulonglong2 wg = sGrad[j + 1];
            u64 pre = ffma2(Y0, wp.x, ffma2(Y1, wp.y, bb));
            float pl, ph; unpack2(pre, pl, ph);
            u64 t = pack2(tanh_ap(pl), tanh_ap(ph));
            u64 t2m = ffma2(t, t, NEG1);
            b0 = ffma2(t2m, wg.x, b0);
            b1 = ffma2(t2m, wg.y, b1);
        }
    }
    G0 = fadd2(a0, b0);
    G1 = fadd2(a1, b1);
}

__global__ void __launch_bounds__(256, 4)
gyro_kernel(const float4* __restrict__ rin, float4* __restrict__ out,
            int B, int half)
{
    __shared__ ulonglong2 sPre [NLAYERS * NEUR];
    __shared__ u64        sBB  [NLAYERS * NEUR];
    __shared__ ulonglong2 sGrad[NLAYERS * NEUR];
    __shared__ float2     seta[NLAYERS];
    __shared__ float2     scs;

    for (int i = threadIdx.x; i < NLAYERS * NEUR; i += blockDim.x) {
        sPre[i]  = g_pre[i];
        sBB[i]   = g_bb[i];
        sGrad[i] = g_grad[i];
    }
    if (threadIdx.x < NLAYERS) seta[threadIdx.x] = g_eta[threadIdx.x];
    if (threadIdx.x == 0)      scs = g_cs;
    __syncthreads();

    int idx = blockIdx.x * blockDim.x + threadIdx.x;
    if (idx >= half) return;
    int idx2 = idx + half;
    bool hasB = (idx2 < B);
    int i2 = hasB ? idx2 : idx;

    const u64 NEG1 = pack2(-1.0f, -1.0f);

    float4 zA = rin[idx];
    float4 zB = rin[i2];
    u64 X0 = pack2(zA.x, zB.x);
    u64 X1 = pack2(zA.y, zB.y);
    u64 Y0 = pack2(zA.z, zB.z);
    u64 Y1 = pack2(zA.w, zB.w);

    // ---- inverse psi layers, l = 7 .. 0 ----
    for (int l = 7; l >= 0; --l) {
        u64 nE0 = pack2(-seta[l].x, -seta[l].x);
        u64 nE1 = pack2(-seta[l].y, -seta[l].y);
        const ulonglong2* wP = &sPre [l * NEUR];
        const u64*        wB = &sBB  [l * NEUR];
        const ulonglong2* wG = &sGrad[l * NEUR];
#pragma unroll 1
        for (int k = 0; k < 4; ++k) {
            u64 Yn0 = fadd2(X0, nE0);
            u64 Yn1 = fadd2(X1, nE1);
            u64 G0, G1;
            grad2x2(wP, wB, wG, Yn0, Yn1, NEG1, G0, G1);
            u64 Nx0 = ffma2(Y0, NEG1, G0);    // G0 - Y0
            u64 Nx1 = ffma2(Y1, NEG1, G1);
            Y0 = Yn0; Y1 = Yn1;
            X0 = Nx0; X1 = Nx1;
        }
    }

    // ---- circle action (acts on q1 = X0, p1 = Y0 of both points) ----
    {
        u64 C  = pack2(scs.x,  scs.x);
        u64 S  = pack2(scs.y,  scs.y);
        u64 nS = pack2(-scs.y, -scs.y);
        u64 q1 = X0, p1 = Y0;
        X0 = ffma2(C, q1, fmul2(S,  p1));
        Y0 = ffma2(C, p1, fmul2(nS, q1));
    }

    // ---- forward layers: l = 0..7 psi, l = 8..15 ni ----
    for (int l = 0; l < NLAYERS; ++l) {
        u64 E0 = pack2(seta[l].x, seta[l].x);
        u64 E1 = pack2(seta[l].y, seta[l].y);
        const ulonglong2* wP = &sPre [l * NEUR];
        const u64*        wB = &sBB  [l * NEUR];
        const ulonglong2* wG = &sGrad[l * NEUR];
#pragma unroll 1
        for (int k = 0; k < 4; ++k) {
            u64 G0, G1;
            grad2x2(wP, wB, wG, Y0, Y1, NEG1, G0, G1);
            u64 Nx0 = fadd2(Y0, E0);
            u64 Nx1 = fadd2(Y1, E1);
            u64 Ny0 = ffma2(X0, NEG1, G0);    // G0 - X0
            u64 Ny1 = ffma2(X1, NEG1, G1);
            X0 = Nx0; X1 = Nx1;
            Y0 = Ny0; Y1 = Ny1;
        }
    }

    float xA0, xB0, xA1, xB1, yA0, yB0, yA1, yB1;
    unpack2(X0, xA0, xB0); unpack2(X1, xA1, xB1);
    unpack2(Y0, yA0, yB0); unpack2(Y1, yA1, yB1);

    out[idx] = make_float4(xA0, xA1, yA0, yA1);
    if (hasB)
        out[idx2] = make_float4(xB0, xB1, yB0, yB1);
}

extern "C" void kernel_launch(void* const* d_in, const int* in_sizes, int n_in,
                              void* d_out, int out_size)
{
    const float* r        = (const float*)d_in[0];
    const float* theta0   = (const float*)d_in[1];
    const float* psi_Win  = (const float*)d_in[2];
    const float* psi_Wout = (const float*)d_in[3];
    const float* psi_b    = (const float*)d_in[4];
    const float* psi_eta  = (const float*)d_in[5];
    const float* ni_Win   = (const float*)d_in[6];
    const float* ni_Wout  = (const float*)d_in[7];
    const float* ni_b     = (const float*)d_in[8];
    const float* ni_eta   = (const float*)d_in[9];

    int B = in_sizes[0] / 4;
    int half = (B + 1) / 2;

    prep_kernel<<<1, 1024>>>(theta0, psi_Win, psi_Wout, psi_b, psi_eta,
                             ni_Win, ni_Wout, ni_b, ni_eta);

    int threads = 256;
    int blocks = (half + threads - 1) / threads;
    gyro_kernel<<<blocks, threads>>>((const float4*)r, (float4*)d_out, B, half);
}